// round 15
// baseline (speedup 1.0000x reference)
#include <cuda_runtime.h>

// Problem constants
#define TOTAL_N 262144      // B*N nodes
#define NEDGE   4194304
#define NEDGE4  1048576     // NEDGE/4 (int4 groups)
#define NPTS    32768
#define CBOUT   128
#define NSTATS  90          // 12 sums + 78 upper-triangle second moments

// Persistent kernel A: 148 SMs x 4 blocks, residency forced by launch_bounds
#define GRID_A  592
#define NT_A    256
#define NTHR_A  (GRID_A * NT_A)     // 151552

// Stats kernel (co-residency for gbar guaranteed: 128 thr, <=255 regs -> >=2/SM)
#define GRID_S  296
#define NT_S    128
#define NTHR_S  (GRID_S * NT_S)     // 37888

// ---------------------------------------------------------------------------
// Device scratch (static allocations only)
// ---------------------------------------------------------------------------
__device__ float  g_deg[TOTAL_N];
__device__ float  g_dis[TOTAL_N];
__device__ float4 g_t0[TOTAL_N];
__device__ float4 g_t1[TOTAL_N];
__device__ float4 g_t2[TOTAL_N];
__device__ float4 g_t3[TOTAL_N];
__device__ float4 g_q[TOTAL_N];     // dis-scaled current Chebyshev vector
__device__ float4 g_acc[TOTAL_N];   // edge-pass accumulator
__device__ double g_statsP[NSTATS * 16];   // one 128B line per stat (LTS spread)
__device__ float  g_wfT[CBOUT * 12];
__device__ float  g_sh[CBOUT];

// software grid barrier state (cnt returns to 0 after each use; gen monotonic)
__device__ int           g_bcnt = 0;
__device__ volatile int  g_bgen = 0;

__device__ __forceinline__ void red_v4(float4* addr, float x, float y, float z) {
    asm volatile("red.global.add.v4.f32 [%0], {%1, %2, %3, %4};"
                 :: "l"(addr), "f"(x), "f"(y), "f"(z), "f"(0.f) : "memory");
}

// packed f32x2 helpers (sm_100+)
__device__ __forceinline__ unsigned long long ffma2(unsigned long long a,
                                                    unsigned long long b,
                                                    unsigned long long c) {
    unsigned long long d;
    asm("fma.rn.f32x2 %0, %1, %2, %3;" : "=l"(d) : "l"(a), "l"(b), "l"(c));
    return d;
}
__device__ __forceinline__ unsigned long long pk2(float lo, float hi) {
    unsigned long long r;
    asm("mov.b64 %0, {%1, %2};" : "=l"(r) : "f"(lo), "f"(hi));
    return r;
}
__device__ __forceinline__ void upk2(float& lo, float& hi, unsigned long long v) {
    asm("mov.b64 {%0, %1}, %2;" : "=f"(lo), "=f"(hi) : "l"(v));
}

// Grid-wide barrier (full grid co-resident per launch_bounds / reg budget).
__device__ __forceinline__ void gbar(int nblk) {
    __syncthreads();
    if (threadIdx.x == 0) {
        __threadfence();
        int gen = g_bgen;
        if (atomicAdd(&g_bcnt, 1) == nblk - 1) {
            g_bcnt = 0;
            __threadfence();
            g_bgen = gen + 1;
        } else {
            while (g_bgen == gen) { __nanosleep(64); }
        }
        __threadfence();
    }
    __syncthreads();
}

// ---------------------------------------------------------------------------
// shared edge-propagation phase: acc[dst] += w * q[src], 8 edges/iteration
// ---------------------------------------------------------------------------
__device__ __forceinline__ void edge_prop(const int4* __restrict__ s4,
                                          const int4* __restrict__ d4,
                                          const float4* __restrict__ w4,
                                          int t) {
    for (int g = t; g < NEDGE4; g += 2 * NTHR_A) {
        int g2 = g + NTHR_A;
        bool ok = (g2 < NEDGE4);
        int4   sa = s4[g], da = d4[g];
        float4 wa = w4[g];
        int4   sb = sa, db = da;
        float4 wb = make_float4(0.f, 0.f, 0.f, 0.f);
        if (ok) { sb = s4[g2]; db = d4[g2]; wb = w4[g2]; }
        wa.x = (sa.x == da.x) ? 0.f : wa.x;
        wa.y = (sa.y == da.y) ? 0.f : wa.y;
        wa.z = (sa.z == da.z) ? 0.f : wa.z;
        wa.w = (sa.w == da.w) ? 0.f : wa.w;
        wb.x = (sb.x == db.x) ? 0.f : wb.x;
        wb.y = (sb.y == db.y) ? 0.f : wb.y;
        wb.z = (sb.z == db.z) ? 0.f : wb.z;
        wb.w = (sb.w == db.w) ? 0.f : wb.w;

        float4 q0 = __ldcg(&g_q[sa.x]);
        float4 q1 = __ldcg(&g_q[sa.y]);
        float4 q2 = __ldcg(&g_q[sa.z]);
        float4 q3 = __ldcg(&g_q[sa.w]);
        float4 q4, q5, q6, q7;
        if (ok) {
            q4 = __ldcg(&g_q[sb.x]);
            q5 = __ldcg(&g_q[sb.y]);
            q6 = __ldcg(&g_q[sb.z]);
            q7 = __ldcg(&g_q[sb.w]);
        }

        red_v4(&g_acc[da.x], wa.x * q0.x, wa.x * q0.y, wa.x * q0.z);
        red_v4(&g_acc[da.y], wa.y * q1.x, wa.y * q1.y, wa.y * q1.z);
        red_v4(&g_acc[da.z], wa.z * q2.x, wa.z * q2.y, wa.z * q2.z);
        red_v4(&g_acc[da.w], wa.w * q3.x, wa.w * q3.y, wa.w * q3.z);
        if (ok) {
            red_v4(&g_acc[db.x], wb.x * q4.x, wb.x * q4.y, wb.x * q4.z);
            red_v4(&g_acc[db.y], wb.y * q5.x, wb.y * q5.y, wb.y * q5.z);
            red_v4(&g_acc[db.z], wb.z * q6.x, wb.z * q6.y, wb.z * q6.z);
            red_v4(&g_acc[db.w], wb.w * q7.x, wb.w * q7.y, wb.w * q7.z);
        }
    }
}

// ---------------------------------------------------------------------------
// Kernel A: init -> deg -> node0 -> e1 -> node1 -> e2 -> node2 -> e3
// (unchanged from the 172.5us-measured version)
// ---------------------------------------------------------------------------
__global__ __launch_bounds__(NT_A, 4) void kA(const float* __restrict__ x,
                                              const int* __restrict__ src,
                                              const int* __restrict__ dst,
                                              const float* __restrict__ ew) {
    const int t = blockIdx.x * NT_A + threadIdx.x;
    const int4*   s4 = (const int4*)src;
    const int4*   d4 = (const int4*)dst;
    const float4* w4 = (const float4*)ew;

    // phase: init
    for (int i = t; i < TOTAL_N; i += NTHR_A) {
        g_deg[i] = 0.f;
        g_acc[i] = make_float4(0.f, 0.f, 0.f, 0.f);
    }
    if (t < NSTATS) g_statsP[t * 16] = 0.0;
    gbar(GRID_A);

    // phase: degree
    for (int g = t; g < NEDGE4; g += 2 * NTHR_A) {
        int g2 = g + NTHR_A;
        bool ok = (g2 < NEDGE4);
        int4   sa = s4[g], da = d4[g];
        float4 wa = w4[g];
        int4   sb = sa, db = da;
        float4 wb = make_float4(0.f, 0.f, 0.f, 0.f);
        if (ok) { sb = s4[g2]; db = d4[g2]; wb = w4[g2]; }
        if (sa.x != da.x) atomicAdd(&g_deg[sa.x], wa.x);
        if (sa.y != da.y) atomicAdd(&g_deg[sa.y], wa.y);
        if (sa.z != da.z) atomicAdd(&g_deg[sa.z], wa.z);
        if (sa.w != da.w) atomicAdd(&g_deg[sa.w], wa.w);
        if (ok) {
            if (sb.x != db.x) atomicAdd(&g_deg[sb.x], wb.x);
            if (sb.y != db.y) atomicAdd(&g_deg[sb.y], wb.y);
            if (sb.z != db.z) atomicAdd(&g_deg[sb.z], wb.z);
            if (sb.w != db.w) atomicAdd(&g_deg[sb.w], wb.w);
        }
    }
    gbar(GRID_A);

    // phase: node0
    for (int i = t; i < TOTAL_N; i += NTHR_A) {
        float dg  = __ldcg(&g_deg[i]);
        float dis = (dg > 0.f) ? rsqrtf(fmaxf(dg, 1e-12f)) : 0.f;
        g_dis[i] = dis;
        int b = i >> 15;
        int n = i & (NPTS - 1);
        const float* xb = x + (size_t)b * 3 * NPTS + n;
        float v0 = xb[0];
        float v1 = xb[NPTS];
        float v2 = xb[2 * NPTS];
        g_t0[i] = make_float4(v0, v1, v2, 0.f);
        g_q[i]  = make_float4(dis * v0, dis * v1, dis * v2, 0.f);
    }
    gbar(GRID_A);

    edge_prop(s4, d4, w4, t);                     // acc = A_w q0
    gbar(GRID_A);

    // phase: node1
    for (int i = t; i < TOTAL_N; i += NTHR_A) {
        float4 a  = __ldcg(&g_acc[i]);
        float dis = g_dis[i];
        float vx = -dis * a.x, vy = -dis * a.y, vz = -dis * a.z;
        g_t1[i]  = make_float4(vx, vy, vz, 0.f);
        g_q[i]   = make_float4(dis * vx, dis * vy, dis * vz, 0.f);
        g_acc[i] = make_float4(0.f, 0.f, 0.f, 0.f);
    }
    gbar(GRID_A);

    edge_prop(s4, d4, w4, t);                     // acc = A_w q1
    gbar(GRID_A);

    // phase: node2
    for (int i = t; i < TOTAL_N; i += NTHR_A) {
        float4 a  = __ldcg(&g_acc[i]);
        float dis = g_dis[i];
        float4 t0 = g_t0[i];
        float vx = -2.f * dis * a.x - t0.x;
        float vy = -2.f * dis * a.y - t0.y;
        float vz = -2.f * dis * a.z - t0.z;
        g_t2[i]  = make_float4(vx, vy, vz, 0.f);
        g_q[i]   = make_float4(dis * vx, dis * vy, dis * vz, 0.f);
        g_acc[i] = make_float4(0.f, 0.f, 0.f, 0.f);
    }
    gbar(GRID_A);

    edge_prop(s4, d4, w4, t);                     // acc = A_w q2
}

// ---------------------------------------------------------------------------
// k_stats_fold: T3 + BN stats (block-level smem reduction), then internal
// grid barrier + BN fold on block 0. One launch for the whole tail prep.
// ---------------------------------------------------------------------------
__global__ __launch_bounds__(NT_S) void k_stats_fold(const float* __restrict__ weight,
                                                     const float* __restrict__ gamma,
                                                     const float* __restrict__ beta) {
    int t = blockIdx.x * NT_S + threadIdx.x;
    float acc[NSTATS];
#pragma unroll
    for (int k = 0; k < NSTATS; k++) acc[k] = 0.f;

    for (int i = t; i < TOTAL_N; i += NTHR_S) {
        float4 a  = g_acc[i];
        float dis = g_dis[i];
        float4 b  = g_t1[i];
        float tx = -2.f * dis * a.x - b.x;
        float ty = -2.f * dis * a.y - b.y;
        float tz = -2.f * dis * a.z - b.z;
        g_t3[i] = make_float4(tx, ty, tz, 0.f);

        float v[12];
        float4 p = g_t0[i]; v[0] = p.x; v[1] = p.y; v[2]  = p.z;
        v[3] = b.x; v[4] = b.y; v[5] = b.z;
        float4 c = g_t2[i]; v[6] = c.x; v[7] = c.y; v[8]  = c.z;
        v[9] = tx; v[10] = ty; v[11] = tz;
        int idx = 12;
#pragma unroll
        for (int p2 = 0; p2 < 12; p2++) {
            acc[p2] += v[p2];
#pragma unroll
            for (int q = p2; q < 12; q++) acc[idx++] += v[p2] * v[q];
        }
    }

    // warp reduce
    int lane = threadIdx.x & 31;
    int wid  = threadIdx.x >> 5;
#pragma unroll
    for (int k = 0; k < NSTATS; k++) {
        float xv = acc[k];
        xv += __shfl_down_sync(0xffffffffu, xv, 16);
        xv += __shfl_down_sync(0xffffffffu, xv, 8);
        xv += __shfl_down_sync(0xffffffffu, xv, 4);
        xv += __shfl_down_sync(0xffffffffu, xv, 2);
        xv += __shfl_down_sync(0xffffffffu, xv, 1);
        acc[k] = xv;
    }

    // block reduce via smem, then ONE double-atomic per stat per block
    __shared__ float part[4][NSTATS];
    if (lane == 0) {
#pragma unroll
        for (int k = 0; k < NSTATS; k++) part[wid][k] = acc[k];
    }
    __syncthreads();
    if (threadIdx.x < NSTATS) {
        int k = threadIdx.x;
        double s = (double)part[0][k] + (double)part[1][k]
                 + (double)part[2][k] + (double)part[3][k];
        atomicAdd(&g_statsP[k * 16], s);
    }

    gbar(GRID_S);

    // BN fold on block 0 (128 channels).
    // shift = beta − m·scale (conv bias cancels against batch mean)
    if (blockIdx.x == 0) {
        __shared__ double S[NSTATS];
        int c = threadIdx.x;
        if (c < NSTATS) S[c] = g_statsP[c * 16];
        __syncthreads();

        double wv[12];
#pragma unroll
        for (int a = 0; a < 12; a++) wv[a] = (double)weight[a * CBOUT + c];

        const double invN = 1.0 / (double)TOTAL_N;
        double m = 0.0;
#pragma unroll
        for (int a = 0; a < 12; a++) m += S[a] * wv[a];
        m *= invN;

        double q = 0.0;
        int idx = 12;
#pragma unroll
        for (int a = 0; a < 12; a++) {
#pragma unroll
            for (int b = a; b < 12; b++) {
                double term = S[idx++] * wv[a] * wv[b];
                q += (a == b) ? term : 2.0 * term;
            }
        }
        q *= invN;

        double var = q - m * m;
        if (var < 0.0) var = 0.0;
        double scale = (double)gamma[c] * rsqrt(var + 1e-5);
        g_sh[c] = (float)((double)beta[c] - m * scale);
#pragma unroll
        for (int a = 0; a < 12; a++)
            g_wfT[c * 12 + a] = (float)(wv[a] * scale);
    }
}

// ---------------------------------------------------------------------------
// k_final: fused GEMV + BN + ReLU with packed f32x2 FMA, 2 nodes/thread.
// 256-node tiles (grid 1024), ~24 packed regs of node data -> high occupancy.
// Stores are STG.64, warp covers 256 contiguous bytes per channel.
// ---------------------------------------------------------------------------
__global__ __launch_bounds__(256) void k_final(float* __restrict__ out) {
    __shared__ __align__(16) float2 swf2[CBOUT * 12];  // duplicated weights
    __shared__ float ssh[CBOUT];

    int tid = threadIdx.x;
    for (int k = tid; k < CBOUT * 12; k += 256) {
        float w = g_wfT[k];
        swf2[k] = make_float2(w, w);
    }
    if (tid < CBOUT) ssh[tid] = g_sh[tid];
    __syncthreads();

    int w    = tid >> 5;
    int lane = tid & 31;
    int nw   = w & 3;                      // node-warp within tile
    int cg   = w >> 2;                     // channel half
    int base = blockIdx.x * 256 + nw * 64 + lane * 2;   // first of 2 nodes

    float4 A0 = g_t0[base], A1 = g_t0[base + 1];
    float4 B0 = g_t1[base], B1 = g_t1[base + 1];
    float4 C0 = g_t2[base], C1 = g_t2[base + 1];
    float4 D0 = g_t3[base], D1 = g_t3[base + 1];

    unsigned long long va[12];
    va[0]  = pk2(A0.x, A1.x);
    va[1]  = pk2(A0.y, A1.y);
    va[2]  = pk2(A0.z, A1.z);
    va[3]  = pk2(B0.x, B1.x);
    va[4]  = pk2(B0.y, B1.y);
    va[5]  = pk2(B0.z, B1.z);
    va[6]  = pk2(C0.x, C1.x);
    va[7]  = pk2(C0.y, C1.y);
    va[8]  = pk2(C0.z, C1.z);
    va[9]  = pk2(D0.x, D1.x);
    va[10] = pk2(D0.y, D1.y);
    va[11] = pk2(D0.z, D1.z);

    int bb = base >> 15;
    int n  = base & (NPTS - 1);
    float* obase = out + ((size_t)bb * CBOUT) * NPTS + n;

#pragma unroll 8
    for (int k = 0; k < 64; k++) {
        int ch = cg * 64 + k;
        const unsigned long long* wr = (const unsigned long long*)(swf2 + ch * 12);
        float sh = ssh[ch];
        unsigned long long r = pk2(sh, sh);
#pragma unroll
        for (int a = 0; a < 12; a++)
            r = ffma2(va[a], wr[a], r);
        float r0, r1;
        upk2(r0, r1, r);
        *(float2*)(obase + (size_t)ch * NPTS) =
            make_float2(fmaxf(r0, 0.f), fmaxf(r1, 0.f));
    }
}

// ---------------------------------------------------------------------------
// launch: 3 kernels total
// ---------------------------------------------------------------------------
extern "C" void kernel_launch(void* const* d_in, const int* in_sizes, int n_in,
                              void* d_out, int out_size) {
    const float* x      = (const float*)d_in[0];
    const int*   eidx   = (const int*)d_in[1];
    const float* ew     = (const float*)d_in[2];
    const float* weight = (const float*)d_in[3];
    const float* gamma  = (const float*)d_in[5];
    const float* beta   = (const float*)d_in[6];
    float* out = (float*)d_out;

    const int* src = eidx;          // edge_index[0]
    const int* dst = eidx + NEDGE;  // edge_index[1]

    kA<<<GRID_A, NT_A>>>(x, src, dst, ew);
    k_stats_fold<<<GRID_S, NT_S>>>(weight, gamma, beta);
    k_final<<<TOTAL_N / 256, 256>>>(out);
}

// round 16
// speedup vs baseline: 1.0446x; 1.0446x over previous
#include <cuda_runtime.h>

// Problem constants
#define TOTAL_N 262144      // B*N nodes
#define NEDGE   4194304
#define NEDGE4  1048576     // NEDGE/4 (int4 groups)
#define NPTS    32768
#define CBOUT   128
#define NSTATS  90          // 12 sums + 78 upper-triangle second moments

// Persistent kernel A: 148 SMs x 4 blocks, residency forced by launch_bounds
#define GRID_A  592
#define NT_A    256
#define NTHR_A  (GRID_A * NT_A)     // 151552

// Stats kernel
#define GRID_S  296
#define NT_S    128
#define NTHR_S  (GRID_S * NT_S)     // 37888

// ---------------------------------------------------------------------------
// Device scratch (static allocations only)
// ---------------------------------------------------------------------------
__device__ float  g_deg[TOTAL_N];
__device__ float  g_dis[TOTAL_N];
__device__ float4 g_t0[TOTAL_N];
__device__ float4 g_t1[TOTAL_N];
__device__ float4 g_t2[TOTAL_N];
__device__ float4 g_t3[TOTAL_N];
__device__ float4 g_q[TOTAL_N];     // dis-scaled current Chebyshev vector
__device__ float4 g_acc[TOTAL_N];   // edge-pass accumulator
__device__ double g_statsP[NSTATS * 16];   // one 128B line per stat (LTS spread)
__device__ float  g_wfT[CBOUT * 12];
__device__ float  g_sh[CBOUT];

// software grid barrier state (cnt returns to 0 after each use; gen monotonic)
__device__ int           g_bcnt = 0;
__device__ volatile int  g_bgen = 0;

__device__ __forceinline__ void red_v4(float4* addr, float x, float y, float z) {
    asm volatile("red.global.add.v4.f32 [%0], {%1, %2, %3, %4};"
                 :: "l"(addr), "f"(x), "f"(y), "f"(z), "f"(0.f) : "memory");
}

// packed f32x2 helpers (sm_100+)
__device__ __forceinline__ unsigned long long ffma2(unsigned long long a,
                                                    unsigned long long b,
                                                    unsigned long long c) {
    unsigned long long d;
    asm("fma.rn.f32x2 %0, %1, %2, %3;" : "=l"(d) : "l"(a), "l"(b), "l"(c));
    return d;
}
__device__ __forceinline__ unsigned long long pk2(float lo, float hi) {
    unsigned long long r;
    asm("mov.b64 %0, {%1, %2};" : "=l"(r) : "f"(lo), "f"(hi));
    return r;
}
__device__ __forceinline__ void upk2(float& lo, float& hi, unsigned long long v) {
    asm("mov.b64 {%0, %1}, %2;" : "=f"(lo), "=f"(hi) : "l"(v));
}

// Grid-wide barrier (full grid co-resident per launch_bounds).
__device__ __forceinline__ void gbar(int nblk) {
    __syncthreads();
    if (threadIdx.x == 0) {
        __threadfence();
        int gen = g_bgen;
        if (atomicAdd(&g_bcnt, 1) == nblk - 1) {
            g_bcnt = 0;
            __threadfence();
            g_bgen = gen + 1;
        } else {
            while (g_bgen == gen) { __nanosleep(64); }
        }
        __threadfence();
    }
    __syncthreads();
}

// ---------------------------------------------------------------------------
// shared edge-propagation phase: acc[dst] += w * q[src], 8 edges/iteration
// ---------------------------------------------------------------------------
__device__ __forceinline__ void edge_prop(const int4* __restrict__ s4,
                                          const int4* __restrict__ d4,
                                          const float4* __restrict__ w4,
                                          int t) {
    for (int g = t; g < NEDGE4; g += 2 * NTHR_A) {
        int g2 = g + NTHR_A;
        bool ok = (g2 < NEDGE4);
        int4   sa = s4[g], da = d4[g];
        float4 wa = w4[g];
        int4   sb = sa, db = da;
        float4 wb = make_float4(0.f, 0.f, 0.f, 0.f);
        if (ok) { sb = s4[g2]; db = d4[g2]; wb = w4[g2]; }
        wa.x = (sa.x == da.x) ? 0.f : wa.x;
        wa.y = (sa.y == da.y) ? 0.f : wa.y;
        wa.z = (sa.z == da.z) ? 0.f : wa.z;
        wa.w = (sa.w == da.w) ? 0.f : wa.w;
        wb.x = (sb.x == db.x) ? 0.f : wb.x;
        wb.y = (sb.y == db.y) ? 0.f : wb.y;
        wb.z = (sb.z == db.z) ? 0.f : wb.z;
        wb.w = (sb.w == db.w) ? 0.f : wb.w;

        float4 q0 = __ldcg(&g_q[sa.x]);
        float4 q1 = __ldcg(&g_q[sa.y]);
        float4 q2 = __ldcg(&g_q[sa.z]);
        float4 q3 = __ldcg(&g_q[sa.w]);
        float4 q4, q5, q6, q7;
        if (ok) {
            q4 = __ldcg(&g_q[sb.x]);
            q5 = __ldcg(&g_q[sb.y]);
            q6 = __ldcg(&g_q[sb.z]);
            q7 = __ldcg(&g_q[sb.w]);
        }

        red_v4(&g_acc[da.x], wa.x * q0.x, wa.x * q0.y, wa.x * q0.z);
        red_v4(&g_acc[da.y], wa.y * q1.x, wa.y * q1.y, wa.y * q1.z);
        red_v4(&g_acc[da.z], wa.z * q2.x, wa.z * q2.y, wa.z * q2.z);
        red_v4(&g_acc[da.w], wa.w * q3.x, wa.w * q3.y, wa.w * q3.z);
        if (ok) {
            red_v4(&g_acc[db.x], wb.x * q4.x, wb.x * q4.y, wb.x * q4.z);
            red_v4(&g_acc[db.y], wb.y * q5.x, wb.y * q5.y, wb.y * q5.z);
            red_v4(&g_acc[db.z], wb.z * q6.x, wb.z * q6.y, wb.z * q6.z);
            red_v4(&g_acc[db.w], wb.w * q7.x, wb.w * q7.y, wb.w * q7.z);
        }
    }
}

// ---------------------------------------------------------------------------
// Kernel A: init(deg) -> deg -> node0(+acc zero) -> e1 -> node1 -> e2 -> node2 -> e3
// ---------------------------------------------------------------------------
__global__ __launch_bounds__(NT_A, 4) void kA(const float* __restrict__ x,
                                              const int* __restrict__ src,
                                              const int* __restrict__ dst,
                                              const float* __restrict__ ew) {
    const int t = blockIdx.x * NT_A + threadIdx.x;
    const int4*   s4 = (const int4*)src;
    const int4*   d4 = (const int4*)dst;
    const float4* w4 = (const float4*)ew;

    // phase: init (deg + stats only; acc is zeroed inside node0)
    for (int i = t; i < TOTAL_N; i += NTHR_A) {
        g_deg[i] = 0.f;
    }
    if (t < NSTATS) g_statsP[t * 16] = 0.0;
    gbar(GRID_A);

    // phase: degree
    for (int g = t; g < NEDGE4; g += 2 * NTHR_A) {
        int g2 = g + NTHR_A;
        bool ok = (g2 < NEDGE4);
        int4   sa = s4[g], da = d4[g];
        float4 wa = w4[g];
        int4   sb = sa, db = da;
        float4 wb = make_float4(0.f, 0.f, 0.f, 0.f);
        if (ok) { sb = s4[g2]; db = d4[g2]; wb = w4[g2]; }
        if (sa.x != da.x) atomicAdd(&g_deg[sa.x], wa.x);
        if (sa.y != da.y) atomicAdd(&g_deg[sa.y], wa.y);
        if (sa.z != da.z) atomicAdd(&g_deg[sa.z], wa.z);
        if (sa.w != da.w) atomicAdd(&g_deg[sa.w], wa.w);
        if (ok) {
            if (sb.x != db.x) atomicAdd(&g_deg[sb.x], wb.x);
            if (sb.y != db.y) atomicAdd(&g_deg[sb.y], wb.y);
            if (sb.z != db.z) atomicAdd(&g_deg[sb.z], wb.z);
            if (sb.w != db.w) atomicAdd(&g_deg[sb.w], wb.w);
        }
    }
    gbar(GRID_A);

    // phase: node0 (also zeroes acc for e1)
    for (int i = t; i < TOTAL_N; i += NTHR_A) {
        float dg  = __ldcg(&g_deg[i]);
        float dis = (dg > 0.f) ? rsqrtf(fmaxf(dg, 1e-12f)) : 0.f;
        g_dis[i] = dis;
        int b = i >> 15;
        int n = i & (NPTS - 1);
        const float* xb = x + (size_t)b * 3 * NPTS + n;
        float v0 = xb[0];
        float v1 = xb[NPTS];
        float v2 = xb[2 * NPTS];
        g_t0[i]  = make_float4(v0, v1, v2, 0.f);
        g_q[i]   = make_float4(dis * v0, dis * v1, dis * v2, 0.f);
        g_acc[i] = make_float4(0.f, 0.f, 0.f, 0.f);
    }
    gbar(GRID_A);

    edge_prop(s4, d4, w4, t);                     // acc = A_w q0
    gbar(GRID_A);

    // phase: node1
    for (int i = t; i < TOTAL_N; i += NTHR_A) {
        float4 a  = __ldcg(&g_acc[i]);
        float dis = g_dis[i];
        float vx = -dis * a.x, vy = -dis * a.y, vz = -dis * a.z;
        g_t1[i]  = make_float4(vx, vy, vz, 0.f);
        g_q[i]   = make_float4(dis * vx, dis * vy, dis * vz, 0.f);
        g_acc[i] = make_float4(0.f, 0.f, 0.f, 0.f);
    }
    gbar(GRID_A);

    edge_prop(s4, d4, w4, t);                     // acc = A_w q1
    gbar(GRID_A);

    // phase: node2
    for (int i = t; i < TOTAL_N; i += NTHR_A) {
        float4 a  = __ldcg(&g_acc[i]);
        float dis = g_dis[i];
        float4 t0 = g_t0[i];
        float vx = -2.f * dis * a.x - t0.x;
        float vy = -2.f * dis * a.y - t0.y;
        float vz = -2.f * dis * a.z - t0.z;
        g_t2[i]  = make_float4(vx, vy, vz, 0.f);
        g_q[i]   = make_float4(dis * vx, dis * vy, dis * vz, 0.f);
        g_acc[i] = make_float4(0.f, 0.f, 0.f, 0.f);
    }
    gbar(GRID_A);

    edge_prop(s4, d4, w4, t);                     // acc = A_w q2
}

// ---------------------------------------------------------------------------
// k_node3_stats: T3 = -2*dis*acc - T1, accumulate Σv and Σvvᵀ.
// Block-level smem reduction -> 90 double-atomics per BLOCK onto padded lines.
// ---------------------------------------------------------------------------
__global__ __launch_bounds__(NT_S) void k_node3_stats() {
    int t = blockIdx.x * NT_S + threadIdx.x;
    float acc[NSTATS];
#pragma unroll
    for (int k = 0; k < NSTATS; k++) acc[k] = 0.f;

    for (int i = t; i < TOTAL_N; i += NTHR_S) {
        float4 a  = g_acc[i];
        float dis = g_dis[i];
        float4 b  = g_t1[i];
        float tx = -2.f * dis * a.x - b.x;
        float ty = -2.f * dis * a.y - b.y;
        float tz = -2.f * dis * a.z - b.z;
        g_t3[i] = make_float4(tx, ty, tz, 0.f);

        float v[12];
        float4 p = g_t0[i]; v[0] = p.x; v[1] = p.y; v[2]  = p.z;
        v[3] = b.x; v[4] = b.y; v[5] = b.z;
        float4 c = g_t2[i]; v[6] = c.x; v[7] = c.y; v[8]  = c.z;
        v[9] = tx; v[10] = ty; v[11] = tz;
        int idx = 12;
#pragma unroll
        for (int p2 = 0; p2 < 12; p2++) {
            acc[p2] += v[p2];
#pragma unroll
            for (int q = p2; q < 12; q++) acc[idx++] += v[p2] * v[q];
        }
    }

    // warp reduce
    int lane = threadIdx.x & 31;
    int wid  = threadIdx.x >> 5;
#pragma unroll
    for (int k = 0; k < NSTATS; k++) {
        float xv = acc[k];
        xv += __shfl_down_sync(0xffffffffu, xv, 16);
        xv += __shfl_down_sync(0xffffffffu, xv, 8);
        xv += __shfl_down_sync(0xffffffffu, xv, 4);
        xv += __shfl_down_sync(0xffffffffu, xv, 2);
        xv += __shfl_down_sync(0xffffffffu, xv, 1);
        acc[k] = xv;
    }

    __shared__ float part[4][NSTATS];
    if (lane == 0) {
#pragma unroll
        for (int k = 0; k < NSTATS; k++) part[wid][k] = acc[k];
    }
    __syncthreads();
    if (threadIdx.x < NSTATS) {
        int k = threadIdx.x;
        double s = (double)part[0][k] + (double)part[1][k]
                 + (double)part[2][k] + (double)part[3][k];
        atomicAdd(&g_statsP[k * 16], s);
    }
}

// ---------------------------------------------------------------------------
// BN fold: exact batch mean/var -> per-channel scale/shift.
// shift = beta − m·scale (conv bias cancels against batch mean)
// ---------------------------------------------------------------------------
__global__ void k_bnparam(const float* __restrict__ weight,  // (12, 128)
                          const float* __restrict__ gamma,
                          const float* __restrict__ beta) {
    __shared__ double S[NSTATS];
    int c = threadIdx.x;                              // 128 threads
    if (c < NSTATS) S[c] = g_statsP[c * 16];
    __syncthreads();

    double wv[12];
#pragma unroll
    for (int a = 0; a < 12; a++) wv[a] = (double)weight[a * CBOUT + c];

    const double invN = 1.0 / (double)TOTAL_N;
    double m = 0.0;
#pragma unroll
    for (int a = 0; a < 12; a++) m += S[a] * wv[a];
    m *= invN;

    double q = 0.0;
    int idx = 12;
#pragma unroll
    for (int a = 0; a < 12; a++) {
#pragma unroll
        for (int b = a; b < 12; b++) {
            double term = S[idx++] * wv[a] * wv[b];
            q += (a == b) ? term : 2.0 * term;
        }
    }
    q *= invN;

    double var = q - m * m;
    if (var < 0.0) var = 0.0;
    double scale = (double)gamma[c] * rsqrt(var + 1e-5);
    g_sh[c] = (float)((double)beta[c] - m * scale);
#pragma unroll
    for (int a = 0; a < 12; a++)
        g_wfT[c * 12 + a] = (float)(wv[a] * scale);
}

// ---------------------------------------------------------------------------
// k_final: fused GEMV + BN + ReLU with packed f32x2 FMA, 4 nodes/thread.
// Block tile = 512 nodes; duplicated weights in smem ({w,w} float2 per term).
// Stores are STG.128 (4 adjacent nodes, same channel).  [R13-measured: 36.6us]
// ---------------------------------------------------------------------------
__global__ __launch_bounds__(256) void k_final(float* __restrict__ out) {
    __shared__ __align__(16) float2 swf2[CBOUT * 12];  // duplicated weights
    __shared__ float ssh[CBOUT];

    int tid = threadIdx.x;
    for (int k = tid; k < CBOUT * 12; k += 256) {
        float w = g_wfT[k];
        swf2[k] = make_float2(w, w);
    }
    if (tid < CBOUT) ssh[tid] = g_sh[tid];
    __syncthreads();

    int w    = tid >> 5;
    int lane = tid & 31;
    int nw   = w & 3;                      // node-warp within tile
    int cg   = w >> 2;                     // channel half
    int base = blockIdx.x * 512 + nw * 128 + lane * 4;   // first of 4 nodes

    float4 A0 = g_t0[base],   A1 = g_t0[base+1], A2 = g_t0[base+2], A3 = g_t0[base+3];
    float4 B0 = g_t1[base],   B1 = g_t1[base+1], B2 = g_t1[base+2], B3 = g_t1[base+3];
    float4 C0 = g_t2[base],   C1 = g_t2[base+1], C2 = g_t2[base+2], C3 = g_t2[base+3];
    float4 D0 = g_t3[base],   D1 = g_t3[base+1], D2 = g_t3[base+2], D3 = g_t3[base+3];

    unsigned long long va01[12], va23[12];
    va01[0]  = pk2(A0.x, A1.x);  va23[0]  = pk2(A2.x, A3.x);
    va01[1]  = pk2(A0.y, A1.y);  va23[1]  = pk2(A2.y, A3.y);
    va01[2]  = pk2(A0.z, A1.z);  va23[2]  = pk2(A2.z, A3.z);
    va01[3]  = pk2(B0.x, B1.x);  va23[3]  = pk2(B2.x, B3.x);
    va01[4]  = pk2(B0.y, B1.y);  va23[4]  = pk2(B2.y, B3.y);
    va01[5]  = pk2(B0.z, B1.z);  va23[5]  = pk2(B2.z, B3.z);
    va01[6]  = pk2(C0.x, C1.x);  va23[6]  = pk2(C2.x, C3.x);
    va01[7]  = pk2(C0.y, C1.y);  va23[7]  = pk2(C2.y, C3.y);
    va01[8]  = pk2(C0.z, C1.z);  va23[8]  = pk2(C2.z, C3.z);
    va01[9]  = pk2(D0.x, D1.x);  va23[9]  = pk2(D2.x, D3.x);
    va01[10] = pk2(D0.y, D1.y);  va23[10] = pk2(D2.y, D3.y);
    va01[11] = pk2(D0.z, D1.z);  va23[11] = pk2(D2.z, D3.z);

    int bb = base >> 15;
    int n  = base & (NPTS - 1);
    float* obase = out + ((size_t)bb * CBOUT) * NPTS + n;

#pragma unroll 4
    for (int k = 0; k < 64; k++) {
        int ch = cg * 64 + k;
        const unsigned long long* wr = (const unsigned long long*)(swf2 + ch * 12);
        float sh = ssh[ch];
        unsigned long long r01 = pk2(sh, sh);
        unsigned long long r23 = r01;
#pragma unroll
        for (int a = 0; a < 12; a++) {
            unsigned long long wd = wr[a];
            r01 = ffma2(va01[a], wd, r01);
            r23 = ffma2(va23[a], wd, r23);
        }
        float r0, r1, r2, r3;
        upk2(r0, r1, r01);
        upk2(r2, r3, r23);
        float4 o = make_float4(fmaxf(r0, 0.f), fmaxf(r1, 0.f),
                               fmaxf(r2, 0.f), fmaxf(r3, 0.f));
        *(float4*)(obase + (size_t)ch * NPTS) = o;
    }
}

// ---------------------------------------------------------------------------
// launch: 4 kernels total (R13 layout + leaner kA init)
// ---------------------------------------------------------------------------
extern "C" void kernel_launch(void* const* d_in, const int* in_sizes, int n_in,
                              void* d_out, int out_size) {
    const float* x      = (const float*)d_in[0];
    const int*   eidx   = (const int*)d_in[1];
    const float* ew     = (const float*)d_in[2];
    const float* weight = (const float*)d_in[3];
    const float* gamma  = (const float*)d_in[5];
    const float* beta   = (const float*)d_in[6];
    float* out = (float*)d_out;

    const int* src = eidx;          // edge_index[0]
    const int* dst = eidx + NEDGE;  // edge_index[1]

    kA<<<GRID_A, NT_A>>>(x, src, dst, ew);
    k_node3_stats<<<GRID_S, NT_S>>>();
    k_bnparam<<<1, 128>>>(weight, gamma, beta);
    k_final<<<TOTAL_N / 512, 256>>>(out);
}